// round 5
// baseline (speedup 1.0000x reference)
#include <cuda_runtime.h>
#include <stdint.h>

// Problem constants (fixed by the reference's setup_inputs)
#define NC     50      // conditions
#define NNEUR  30000   // neurons
#define TFULL  600     // full time length of spikes
#define TUSE   500     // T_END_MS - T_START_MS
#define NBINS  16      // len(BIN_MS)
#define MAXSEL 4096
#define EPS_F  1e-7f

#define WARPS_PER_BLK 16
#define TSPLIT ((TUSE + WARPS_PER_BLK - 1) / WARPS_PER_BLK)   // 32 y-blocks per condition

// Safe probe length: NC*NNEUR bytes = 1.5 MB is in-bounds whether the mask
// buffer holds 1.5M uint8, 1.5M int32, or 1.5M float32 elements.
#define PROBE_WORDS ((NC * NNEUR) / 4)

__device__ __constant__ int c_bins[NBINS] = {1,1,2,3,4,6,9,13,18,26,38,55,78,113,162,234};

// Scratch (static device arrays — no allocation allowed)
__device__ float g_selected[NC * TUSE];
__device__ float g_fanos_c[NC * NBINS];
__device__ int   g_f32_ok;            // all probe words, as float, in {0.0, 1.0}
__device__ int   g_i32_ok;            // all probe words, as int,   in {0, 1}
__device__ int   g_idx[NC * MAXSEL];  // compacted selected-neuron indices per condition
__device__ int   g_nsel[NC];
__device__ int   g_trials[NC];        // sanitized trial indices

// ---------------------------------------------------------------------------
// K0a: init probe flags + sanitize trial indices (fused; no data dependence
// on the probe). A valid trial index is in [0, 8). If the buffer were
// float-encoded, nonzero indices reinterpret as ints >= 0x3F800000 (huge),
// detected per element; 0 is identical under both encodings.
// ---------------------------------------------------------------------------
__global__ void k_init(const void* __restrict__ trials)
{
    const int c = threadIdx.x;
    if (c == 0) { g_f32_ok = 1; g_i32_ok = 1; }
    if (c < NC) {
        int iv = ((const int*)trials)[c];
        if (iv < 0 || iv >= 8) iv = (int)(((const float*)trials)[c]);
        g_trials[c] = iv;
    }
}

// ---------------------------------------------------------------------------
// K0b: three-way mask dtype probe over the first 1.5 MB.
//  float32 0/1 mask: words as float in {0,1}; as int contains 0x3F800000 -> i32 fails
//  int32   0/1 mask: words as int in {0,1};  as float contains denormals -> f32 fails
//  uint8   0/1 mask: words as int contain e.g. 0x100/0x10000 (selected neuron at
//                    byte offset %4 != 0; density guarantees many in 1.5MB) -> both fail
// ---------------------------------------------------------------------------
__global__ void k_probe(const void* __restrict__ mask)
{
    const float* mf = (const float*)mask;
    const int*   mi = (const int*)mask;
    int fbad = 0, ibad = 0;
    for (int i = blockIdx.x * blockDim.x + threadIdx.x; i < PROBE_WORDS;
         i += gridDim.x * blockDim.x) {
        float f = mf[i];
        int   v = mi[i];
        if (f != 0.0f && f != 1.0f) fbad = 1;
        if (v != 0 && v != 1)       ibad = 1;
    }
    if (__syncthreads_or(fbad) && threadIdx.x == 0) atomicExch(&g_f32_ok, 0);
    __syncthreads();
    if (__syncthreads_or(ibad) && threadIdx.x == 0) atomicExch(&g_i32_ok, 0);
}

// ---------------------------------------------------------------------------
// K1a: compact mask row -> index list in global scratch. One block/condition.
// Order within the list is arbitrary; downstream sums of 0/1 spike values are
// exact in fp32 so order cannot change the result.
// ---------------------------------------------------------------------------
__global__ void __launch_bounds__(512)
k_compact(const void* __restrict__ mask)
{
    __shared__ int s_n;
    const int c   = blockIdx.x;
    const int tid = threadIdx.x;
    if (tid == 0) s_n = 0;
    __syncthreads();

    // mode: 0 = float32, 1 = int32, 2 = uint8
    const int mode = g_f32_ok ? 0 : (g_i32_ok ? 1 : 2);
    int* out = g_idx + c * MAXSEL;

    if (mode == 0) {
        const float* mrow = (const float*)mask + (size_t)c * NNEUR;
        for (int n = tid; n < NNEUR; n += blockDim.x)
            if (mrow[n] != 0.0f) {
                int p = atomicAdd(&s_n, 1);
                if (p < MAXSEL) out[p] = n;
            }
    } else if (mode == 1) {
        const int* mrow = (const int*)mask + (size_t)c * NNEUR;
        for (int n = tid; n < NNEUR; n += blockDim.x)
            if (mrow[n] != 0) {
                int p = atomicAdd(&s_n, 1);
                if (p < MAXSEL) out[p] = n;
            }
    } else {
        const uint8_t* mrow = (const uint8_t*)mask + (size_t)c * NNEUR;
        for (int n = tid; n < NNEUR; n += blockDim.x)
            if (mrow[n]) {
                int p = atomicAdd(&s_n, 1);
                if (p < MAXSEL) out[p] = n;
            }
    }
    __syncthreads();
    if (tid == 0) g_nsel[c] = min(s_n, MAXSEL);
}

// ---------------------------------------------------------------------------
// K1b: gather. Grid (NC, TSPLIT), 512 threads = 16 warps; each warp computes
// one timestep: lanes stride the ~70-entry index list, shuffle-reduce.
// selected[c,t] = sum_{n in S_c} spikes[trial_c, t, n]
// ---------------------------------------------------------------------------
__global__ void __launch_bounds__(WARPS_PER_BLK * 32)
k_gather(const float* __restrict__ spikes)
{
    __shared__ int s_idx[512];     // covers typical nsel (~15..160); spill path below
    const int c    = blockIdx.x;
    const int tid  = threadIdx.x;
    const int wid  = tid >> 5;
    const int lane = tid & 31;

    const int nsel = g_nsel[c];
    const int* idx_g = g_idx + c * MAXSEL;
    const int ncache = nsel < 512 ? nsel : 512;
    for (int j = tid; j < ncache; j += blockDim.x) s_idx[j] = idx_g[j];
    __syncthreads();

    const int t = blockIdx.y * WARPS_PER_BLK + wid;
    if (t >= TUSE) return;

    const int b = g_trials[c];
    const float* row = spikes + ((size_t)b * TFULL + t) * NNEUR;

    float s = 0.f;
    int j = lane;
    for (; j < ncache; j += 32) s += __ldg(row + s_idx[j]);
    for (; j < nsel;   j += 32) s += __ldg(row + __ldg(idx_g + j));

    #pragma unroll
    for (int o = 16; o > 0; o >>= 1)
        s += __shfl_down_sync(0xffffffffu, s, o);
    if (lane == 0) g_selected[c * TUSE + t] = s;
}

// ---------------------------------------------------------------------------
// K2: per-condition Fano factors for all 16 bin sizes.
// Deterministic tree reductions, two-pass variance (matches jnp.var ddof=0).
// ---------------------------------------------------------------------------
__global__ void __launch_bounds__(512)
k_fano()
{
    __shared__ float sel[512];
    __shared__ float cnt[512];
    __shared__ float red[512];
    const int c   = blockIdx.x;
    const int tid = threadIdx.x;

    sel[tid] = (tid < TUSE) ? g_selected[c * TUSE + tid] : 0.f;
    __syncthreads();

    for (int bi = 0; bi < NBINS; bi++) {
        const int b  = c_bins[bi];
        const int nb = TUSE / b;

        float cv = 0.f;
        if (tid < nb) {
            const int base = tid * b;
            for (int i = 0; i < b; i++) cv += sel[base + i];
        }
        cnt[tid] = (tid < nb) ? cv : 0.f;
        red[tid] = cnt[tid];
        __syncthreads();
        for (int s = 256; s > 0; s >>= 1) {
            if (tid < s) red[tid] += red[tid + s];
            __syncthreads();
        }
        const float mean = red[0] / (float)nb;
        __syncthreads();

        float d = (tid < nb) ? (cnt[tid] - mean) : 0.f;
        red[tid] = d * d;
        __syncthreads();
        for (int s = 256; s > 0; s >>= 1) {
            if (tid < s) red[tid] += red[tid + s];
            __syncthreads();
        }
        if (tid == 0) {
            const float var = red[0] / (float)nb;
            g_fanos_c[c * NBINS + bi] = var / fmaxf(mean, EPS_F);
        }
        __syncthreads();
    }
}

// ---------------------------------------------------------------------------
// K3: final loss = SYNC_COST * mean((exp_fanos - mean_c(fano))^2)
// ---------------------------------------------------------------------------
__global__ void k_loss(const float* __restrict__ exp_fanos, float* __restrict__ out)
{
    const int lane = threadIdx.x;
    float sq = 0.f;
    if (lane < NBINS) {
        float s = 0.f;
        for (int c = 0; c < NC; c++) s += g_fanos_c[c * NBINS + lane];
        const float fano = s / (float)NC;
        const float d = exp_fanos[lane] - fano;
        sq = d * d;
    }
    #pragma unroll
    for (int o = 16; o > 0; o >>= 1)
        sq += __shfl_down_sync(0xffffffffu, sq, o);
    if (lane == 0) out[0] = 10.0f * (sq / (float)NBINS);
}

// ---------------------------------------------------------------------------
extern "C" void kernel_launch(void* const* d_in, const int* in_sizes, int n_in,
                              void* d_out, int out_size)
{
    // Identify inputs by element count (robust to metadata ordering):
    //   spikes: 8*600*30000 = 144,000,000
    //   exp_fanos: 16
    //   sample_trials: 50
    //   sel_mask: 50*30000 = 1,500,000
    const float* spikes    = nullptr;
    const float* exp_fanos = nullptr;
    const void*  trials    = nullptr;
    const void*  mask      = nullptr;
    for (int i = 0; i < n_in; i++) {
        switch (in_sizes[i]) {
            case 144000000: spikes    = (const float*)d_in[i]; break;
            case 16:        exp_fanos = (const float*)d_in[i]; break;
            case 50:        trials    = d_in[i];               break;
            case 1500000:   mask      = d_in[i];               break;
            default: break;
        }
    }
    float* out = (float*)d_out;

    k_init<<<1, 64>>>(trials);
    k_probe<<<128, 256>>>(mask);
    k_compact<<<NC, 512>>>(mask);
    dim3 ggrid(NC, TSPLIT);
    k_gather<<<ggrid, WARPS_PER_BLK * 32>>>(spikes);
    k_fano<<<NC, 512>>>();
    k_loss<<<1, 32>>>(exp_fanos, out);
}

// round 6
// speedup vs baseline: 1.4493x; 1.4493x over previous
#include <cuda_runtime.h>
#include <stdint.h>

// Problem constants (fixed by the reference's setup_inputs)
#define NC     50      // conditions
#define NNEUR  30000   // neurons (divisible by 4 -> int4 loads)
#define TFULL  600     // full time length of spikes
#define TUSE   500     // T_END_MS - T_START_MS
#define NBINS  16      // len(BIN_MS)
#define MAXSEL 4096
#define EPS_F  1e-7f

#define WARPS_PER_BLK 16                                      // == NBINS (warp-per-bin fano)
#define TSPLIT ((TUSE + WARPS_PER_BLK - 1) / WARPS_PER_BLK)   // 32 y-blocks per condition

__device__ __constant__ int c_bins[NBINS] = {1,1,2,3,4,6,9,13,18,26,38,55,78,113,162,234};

// Scratch (static device arrays — no allocation allowed)
__device__ float g_selected[NC * TUSE];
__device__ float g_fanos_c[NC * NBINS];
__device__ int   g_idx[NC * MAXSEL];  // compacted selected-neuron indices per condition
__device__ int   g_nsel[NC];
__device__ int   g_trials[NC];        // sanitized trial indices
__device__ int   g_done[NC];          // per-condition completion counters (reset in k_compact)
__device__ int   g_done2;             // cross-condition completion counter

// ---------------------------------------------------------------------------
// K1: compact mask row -> index list. One block per condition.
// The mask holds a 0/1 bool in 4-byte elements (proved in R5: u8 interpretation
// gives wrong results, so elements are 4 bytes; and for 0/1 data "32-bit word
// != 0" is the selection predicate under BOTH float32 (1.0f=0x3F800000) and
// int32 (1) encodings — no dtype probe needed).
// Also: sanitizes trial indices and resets the completion counters for K2
// (kernel boundary = happens-before the gather's atomics).
// List order is arbitrary; downstream sums of 0/1 spike values are exact in
// fp32 so order cannot change the result.
// ---------------------------------------------------------------------------
__global__ void __launch_bounds__(512)
k_compact(const int* __restrict__ mask, const void* __restrict__ trials)
{
    __shared__ int s_n;
    const int c   = blockIdx.x;
    const int tid = threadIdx.x;

    if (tid == 0) { s_n = 0; g_done[c] = 0; }
    if (c == 0) {
        if (tid == 0) g_done2 = 0;
        if (tid < NC) {
            // Valid trial index in [0,8). If float-encoded, nonzero values
            // reinterpret as ints >= 0x3F800000 -> out of range -> convert.
            int iv = ((const int*)trials)[tid];
            if (iv < 0 || iv >= 8) iv = (int)(((const float*)trials)[tid]);
            g_trials[tid] = iv;
        }
    }
    __syncthreads();

    // Row base: c*NNEUR*4 bytes = c*120000, 16B-aligned -> int4 loads OK.
    const int4* m4 = (const int4*)(mask + (size_t)c * NNEUR);
    int* out = g_idx + c * MAXSEL;
    for (int i = tid; i < NNEUR / 4; i += 512) {
        int4 v = m4[i];
        int n = 4 * i;
        if (v.x) { int p = atomicAdd(&s_n, 1); if (p < MAXSEL) out[p] = n;     }
        if (v.y) { int p = atomicAdd(&s_n, 1); if (p < MAXSEL) out[p] = n + 1; }
        if (v.z) { int p = atomicAdd(&s_n, 1); if (p < MAXSEL) out[p] = n + 2; }
        if (v.w) { int p = atomicAdd(&s_n, 1); if (p < MAXSEL) out[p] = n + 3; }
    }
    __syncthreads();
    if (tid == 0) g_nsel[c] = min(s_n, MAXSEL);
}

// ---------------------------------------------------------------------------
// K2: fused gather + fano + loss.
// Grid (NC, TSPLIT), 512 threads = 16 warps; each warp gathers one timestep:
//   selected[c,t] = sum_{n in S_c} spikes[trial_c, t, n]
// The last block per condition (threadfence+atomic counter) computes that
// condition's 16 Fano factors (warp-per-bin, shuffle-only, two-pass variance
// matching jnp.var ddof=0). The last condition to finish computes the loss.
// ---------------------------------------------------------------------------
__global__ void __launch_bounds__(WARPS_PER_BLK * 32)
k_gather(const float* __restrict__ spikes,
         const float* __restrict__ exp_fanos,
         float* __restrict__ out)
{
    __shared__ int   s_idx[512];     // covers typical nsel (~15..250); spill path below
    __shared__ float sel[TUSE];
    __shared__ int   s_last;
    const int c    = blockIdx.x;
    const int tid  = threadIdx.x;
    const int wid  = tid >> 5;
    const int lane = tid & 31;

    const int nsel = g_nsel[c];
    const int* idx_g = g_idx + c * MAXSEL;
    const int ncache = nsel < 512 ? nsel : 512;
    for (int j = tid; j < ncache; j += blockDim.x) s_idx[j] = idx_g[j];
    __syncthreads();

    const int t = blockIdx.y * WARPS_PER_BLK + wid;
    if (t < TUSE) {
        const float* row = spikes + ((size_t)g_trials[c] * TFULL + t) * NNEUR;
        float s = 0.f;
        int j = lane;
        for (; j < ncache; j += 32) s += __ldg(row + s_idx[j]);
        for (; j < nsel;   j += 32) s += __ldg(row + __ldg(idx_g + j));
        #pragma unroll
        for (int o = 16; o > 0; o >>= 1)
            s += __shfl_down_sync(0xffffffffu, s, o);
        if (lane == 0) g_selected[c * TUSE + t] = s;
    }

    // --- per-condition completion: last block computes fano for c ---
    __threadfence();
    __syncthreads();
    if (tid == 0) s_last = (atomicAdd(&g_done[c], 1) == (int)gridDim.y - 1);
    __syncthreads();
    if (!s_last) return;

    for (int i = tid; i < TUSE; i += blockDim.x) sel[i] = g_selected[c * TUSE + i];
    __syncthreads();

    {   // warp 'wid' owns bin 'wid' — shuffle-only, no block barriers
        const int b  = c_bins[wid];
        const int nb = TUSE / b;

        float sum = 0.f;
        for (int k = lane; k < nb; k += 32) {
            float cv = 0.f;
            const int base = k * b;
            for (int i = 0; i < b; i++) cv += sel[base + i];
            sum += cv;
        }
        #pragma unroll
        for (int o = 16; o > 0; o >>= 1)
            sum += __shfl_down_sync(0xffffffffu, sum, o);
        const float mean = __shfl_sync(0xffffffffu, sum, 0) / (float)nb;

        float vs = 0.f;
        for (int k = lane; k < nb; k += 32) {
            float cv = 0.f;
            const int base = k * b;
            for (int i = 0; i < b; i++) cv += sel[base + i];
            const float d = cv - mean;
            vs += d * d;
        }
        #pragma unroll
        for (int o = 16; o > 0; o >>= 1)
            vs += __shfl_down_sync(0xffffffffu, vs, o);
        if (lane == 0)
            g_fanos_c[c * NBINS + wid] = (vs / (float)nb) / fmaxf(mean, EPS_F);
    }

    // --- cross-condition completion: last condition computes the loss ---
    __threadfence();
    __syncthreads();
    if (tid == 0) s_last = (atomicAdd(&g_done2, 1) == NC - 1);
    __syncthreads();
    if (!s_last) return;

    if (wid == 0) {
        float sq = 0.f;
        if (lane < NBINS) {
            float ssum = 0.f;
            for (int cc = 0; cc < NC; cc++) ssum += g_fanos_c[cc * NBINS + lane];
            const float fano = ssum / (float)NC;
            const float d = exp_fanos[lane] - fano;
            sq = d * d;
        }
        #pragma unroll
        for (int o = 16; o > 0; o >>= 1)
            sq += __shfl_down_sync(0xffffffffu, sq, o);
        if (lane == 0) out[0] = 10.0f * (sq / (float)NBINS);
    }
}

// ---------------------------------------------------------------------------
extern "C" void kernel_launch(void* const* d_in, const int* in_sizes, int n_in,
                              void* d_out, int out_size)
{
    // Identify inputs by element count (robust to metadata ordering):
    //   spikes: 8*600*30000 = 144,000,000
    //   exp_fanos: 16
    //   sample_trials: 50
    //   sel_mask: 50*30000 = 1,500,000
    const float* spikes    = nullptr;
    const float* exp_fanos = nullptr;
    const void*  trials    = nullptr;
    const int*   mask      = nullptr;
    for (int i = 0; i < n_in; i++) {
        switch (in_sizes[i]) {
            case 144000000: spikes    = (const float*)d_in[i]; break;
            case 16:        exp_fanos = (const float*)d_in[i]; break;
            case 50:        trials    = d_in[i];               break;
            case 1500000:   mask      = (const int*)d_in[i];   break;
            default: break;
        }
    }
    float* out = (float*)d_out;

    k_compact<<<NC, 512>>>(mask, trials);
    dim3 ggrid(NC, TSPLIT);
    k_gather<<<ggrid, WARPS_PER_BLK * 32>>>(spikes, exp_fanos, out);
}

// round 8
// speedup vs baseline: 1.4837x; 1.0237x over previous
#include <cuda_runtime.h>
#include <stdint.h>

// Problem constants (fixed by the reference's setup_inputs)
#define NC     50      // conditions
#define NNEUR  30000   // neurons (divisible by 4 -> int4 loads)
#define TFULL  600     // full time length of spikes
#define TUSE   500     // T_END_MS - T_START_MS
#define NBINS  16      // len(BIN_MS)
#define MAXSEL 4096
#define EPS_F  1e-7f

#define WARPS_PER_BLK 16                                      // == NBINS (warp-per-bin fano)
#define TSPLIT ((TUSE + WARPS_PER_BLK - 1) / WARPS_PER_BLK)   // 32 y-blocks per condition

__device__ __constant__ int c_bins[NBINS] = {1,1,2,3,4,6,9,13,18,26,38,55,78,113,162,234};

// Scratch (static device arrays — no allocation allowed)
__device__ float g_selected[NC * TUSE];
__device__ float g_fanos_c[NC * NBINS];
__device__ int   g_idx[NC * MAXSEL];  // compacted selected-neuron indices per condition
__device__ int   g_nsel[NC];
__device__ int   g_trials[NC];        // sanitized trial indices
__device__ int   g_done[NC];          // per-condition completion counters (reset in k_compact)
__device__ int   g_done2;             // cross-condition completion counter

// ---------------------------------------------------------------------------
// Release-scoped atomic add (gpu scope): publishes this thread's prior writes
// WITHOUT the CCTL.IVALL L1-flush that __threadfence() emits. The acquire
// side is a single fence.acq_rel.gpu executed only by the winning block.
// ---------------------------------------------------------------------------
__device__ __forceinline__ int atomic_add_release_gpu(int* p, int v)
{
    int old;
    asm volatile("atom.release.gpu.add.s32 %0, [%1], %2;"
                 : "=r"(old) : "l"(p), "r"(v) : "memory");
    return old;
}
__device__ __forceinline__ void fence_acq_rel_gpu()
{
    asm volatile("fence.acq_rel.gpu;" ::: "memory");
}

// ---------------------------------------------------------------------------
// K1: compact mask row -> index list. One block per condition.
// The mask holds a 0/1 bool in 4-byte elements (proved in R5: u8 reads give
// wrong results; and "32-bit word != 0" is the selection predicate under both
// float32 (1.0f=0x3F800000) and int32 encodings — no dtype probe needed).
// Also sanitizes trial indices and resets the completion counters for K2
// (kernel boundary = happens-before the gather's atomics).
// List order is arbitrary; downstream sums of 0/1 spike values are exact in
// fp32 so order cannot change the result.
// ---------------------------------------------------------------------------
__global__ void __launch_bounds__(512)
k_compact(const int* __restrict__ mask, const void* __restrict__ trials)
{
    __shared__ int s_n;
    const int c   = blockIdx.x;
    const int tid = threadIdx.x;

    if (tid == 0) { s_n = 0; g_done[c] = 0; }
    if (c == 0) {
        if (tid == 0) g_done2 = 0;
        if (tid < NC) {
            // Valid trial index in [0,8). If float-encoded, nonzero values
            // reinterpret as ints >= 0x3F800000 -> out of range -> convert.
            int iv = ((const int*)trials)[tid];
            if (iv < 0 || iv >= 8) iv = (int)(((const float*)trials)[tid]);
            g_trials[tid] = iv;
        }
    }
    __syncthreads();

    // Row base: c*NNEUR*4 bytes, 16B-aligned -> int4 loads OK.
    const int4* m4 = (const int4*)(mask + (size_t)c * NNEUR);
    int* out = g_idx + c * MAXSEL;
    for (int i = tid; i < NNEUR / 4; i += 512) {
        int4 v = m4[i];
        int n = 4 * i;
        if (v.x) { int p = atomicAdd(&s_n, 1); if (p < MAXSEL) out[p] = n;     }
        if (v.y) { int p = atomicAdd(&s_n, 1); if (p < MAXSEL) out[p] = n + 1; }
        if (v.z) { int p = atomicAdd(&s_n, 1); if (p < MAXSEL) out[p] = n + 2; }
        if (v.w) { int p = atomicAdd(&s_n, 1); if (p < MAXSEL) out[p] = n + 3; }
    }
    __syncthreads();
    if (tid == 0) g_nsel[c] = min(s_n, MAXSEL);
}

// ---------------------------------------------------------------------------
// K2: fused gather + fano + loss.
// Grid (NC, TSPLIT), 512 threads = 16 warps; each warp gathers one timestep:
//   selected[c,t] = sum_{n in S_c} spikes[trial_c, t, n]
// Last block per condition (release-atomic counter + consumer-side acquire
// fence) computes that condition's 16 Fano factors (warp-per-bin, shuffle-only,
// two-pass variance matching jnp.var ddof=0). The last condition computes the
// final loss.
// ---------------------------------------------------------------------------
__global__ void __launch_bounds__(WARPS_PER_BLK * 32)
k_gather(const float* __restrict__ spikes,
         const float* __restrict__ exp_fanos,
         float* __restrict__ out)
{
    __shared__ int   s_idx[512];     // covers typical nsel (~15..250); spill path below
    __shared__ float sel[TUSE];
    __shared__ int   s_last;
    const int c    = blockIdx.x;
    const int tid  = threadIdx.x;
    const int wid  = tid >> 5;
    const int lane = tid & 31;

    const int nsel = g_nsel[c];
    const int* idx_g = g_idx + c * MAXSEL;
    const int ncache = nsel < 512 ? nsel : 512;
    for (int j = tid; j < ncache; j += blockDim.x) s_idx[j] = idx_g[j];
    __syncthreads();

    const int t = blockIdx.y * WARPS_PER_BLK + wid;
    if (t < TUSE) {
        const float* row = spikes + ((size_t)g_trials[c] * TFULL + t) * NNEUR;
        float s = 0.f;
        int j = lane;
        for (; j < ncache; j += 32) s += __ldg(row + s_idx[j]);
        for (; j < nsel;   j += 32) s += __ldg(row + __ldg(idx_g + j));
        #pragma unroll
        for (int o = 16; o > 0; o >>= 1)
            s += __shfl_down_sync(0xffffffffu, s, o);
        if (lane == 0) g_selected[c * TUSE + t] = s;
    }

    // --- per-condition completion: last block computes fano for c.
    //     __syncthreads (intra-block HB) -> release-RMW publishes the block's
    //     g_selected writes; NO L1 flush on the 1599 non-last blocks.
    __syncthreads();
    if (tid == 0) s_last = (atomic_add_release_gpu(&g_done[c], 1) == (int)gridDim.y - 1);
    __syncthreads();
    if (!s_last) return;
    if (tid == 0) fence_acq_rel_gpu();   // acquire side, 50 blocks total
    __syncthreads();

    for (int i = tid; i < TUSE; i += blockDim.x) sel[i] = g_selected[c * TUSE + i];
    __syncthreads();

    {   // warp 'wid' owns bin 'wid' — shuffle-only, no block barriers
        const int b  = c_bins[wid];
        const int nb = TUSE / b;

        float sum = 0.f;
        for (int k = lane; k < nb; k += 32) {
            float cv = 0.f;
            const int base = k * b;
            for (int i = 0; i < b; i++) cv += sel[base + i];
            sum += cv;
        }
        #pragma unroll
        for (int o = 16; o > 0; o >>= 1)
            sum += __shfl_down_sync(0xffffffffu, sum, o);
        const float mean = __shfl_sync(0xffffffffu, sum, 0) / (float)nb;

        float vs = 0.f;
        for (int k = lane; k < nb; k += 32) {
            float cv = 0.f;
            const int base = k * b;
            for (int i = 0; i < b; i++) cv += sel[base + i];
            const float d = cv - mean;
            vs += d * d;
        }
        #pragma unroll
        for (int o = 16; o > 0; o >>= 1)
            vs += __shfl_down_sync(0xffffffffu, vs, o);
        if (lane == 0)
            g_fanos_c[c * NBINS + wid] = (vs / (float)nb) / fmaxf(mean, EPS_F);
    }

    // --- cross-condition completion: last condition computes the loss ---
    __syncthreads();
    if (tid == 0) s_last = (atomic_add_release_gpu(&g_done2, 1) == NC - 1);
    __syncthreads();
    if (!s_last) return;
    if (tid == 0) fence_acq_rel_gpu();   // acquire side, 1 block
    __syncthreads();

    if (wid == 0) {
        float sq = 0.f;
        if (lane < NBINS) {
            float ssum = 0.f;
            for (int cc = 0; cc < NC; cc++) ssum += g_fanos_c[cc * NBINS + lane];
            const float fano = ssum / (float)NC;
            const float d = exp_fanos[lane] - fano;
            sq = d * d;
        }
        #pragma unroll
        for (int o = 16; o > 0; o >>= 1)
            sq += __shfl_down_sync(0xffffffffu, sq, o);
        if (lane == 0) out[0] = 10.0f * (sq / (float)NBINS);
    }
}

// ---------------------------------------------------------------------------
extern "C" void kernel_launch(void* const* d_in, const int* in_sizes, int n_in,
                              void* d_out, int out_size)
{
    // Identify inputs by element count (robust to metadata ordering):
    //   spikes: 8*600*30000 = 144,000,000
    //   exp_fanos: 16
    //   sample_trials: 50
    //   sel_mask: 50*30000 = 1,500,000
    const float* spikes    = nullptr;
    const float* exp_fanos = nullptr;
    const void*  trials    = nullptr;
    const int*   mask      = nullptr;
    for (int i = 0; i < n_in; i++) {
        switch (in_sizes[i]) {
            case 144000000: spikes    = (const float*)d_in[i]; break;
            case 16:        exp_fanos = (const float*)d_in[i]; break;
            case 50:        trials    = d_in[i];               break;
            case 1500000:   mask      = (const int*)d_in[i];   break;
            default: break;
        }
    }
    float* out = (float*)d_out;

    k_compact<<<NC, 512>>>(mask, trials);
    dim3 ggrid(NC, TSPLIT);
    k_gather<<<ggrid, WARPS_PER_BLK * 32>>>(spikes, exp_fanos, out);
}

// round 9
// speedup vs baseline: 1.6148x; 1.0883x over previous
#include <cuda_runtime.h>
#include <stdint.h>

// Problem constants (fixed by the reference's setup_inputs)
#define NC     50      // conditions
#define NNEUR  30000   // neurons (4-byte 0/1 elements; established R5)
#define TFULL  600     // full time length of spikes
#define TUSE   500     // T_END_MS - T_START_MS
#define NBINS  16      // len(BIN_MS)
#define MAXSEL 4096
#define EPS_F  1e-7f

#define WARPS_PER_BLK 16                                      // == NBINS
#define TSPLIT ((TUSE + WARPS_PER_BLK - 1) / WARPS_PER_BLK)   // 32 y-blocks per condition
#define CSPLIT 6                                              // compact y-split (30000/6 = 5000, /4 = 1250 int4)
#define CPAD   32                                             // counter padding (128 B) to dodge LTS atomic serialization

__device__ __constant__ int c_bins[NBINS] = {1,1,2,3,4,6,9,13,18,26,38,55,78,113,162,234};

// Scratch (static device arrays — no allocation allowed)
__device__ float g_selected[NC * TUSE];
__device__ float g_fanos_c[NC * NBINS];
__device__ int   g_idx[NC * MAXSEL];     // compacted selected-neuron indices per condition
__device__ int   g_nsel_pad[NC * CPAD];  // padded per-condition counters
__device__ int   g_trials[NC];           // sanitized trial indices
__device__ int   g_done2;                // fano completion counter (for fused loss)

// Release-scoped atomic + acquire fence: last-block pattern without the
// CCTL.IVALL L1-flush of __threadfence().
__device__ __forceinline__ int atomic_add_release_gpu(int* p, int v)
{
    int old;
    asm volatile("atom.release.gpu.add.s32 %0, [%1], %2;"
                 : "=r"(old) : "l"(p), "r"(v) : "memory");
    return old;
}
__device__ __forceinline__ void fence_acq_rel_gpu()
{
    asm volatile("fence.acq_rel.gpu;" ::: "memory");
}

// ---------------------------------------------------------------------------
// K0: reset counters + sanitize trial indices. One block.
// ---------------------------------------------------------------------------
__global__ void __launch_bounds__(512)
k_init(const void* __restrict__ trials)
{
    const int tid = threadIdx.x;
    for (int i = tid; i < NC * CPAD; i += 512) g_nsel_pad[i] = 0;
    if (tid == 0) g_done2 = 0;
    if (tid < NC) {
        // Valid trial index in [0,8). If float-encoded, nonzero values
        // reinterpret as ints >= 0x3F800000 -> out of range -> convert.
        int iv = ((const int*)trials)[tid];
        if (iv < 0 || iv >= 8) iv = (int)(((const float*)trials)[tid]);
        g_trials[tid] = iv;
    }
}

// ---------------------------------------------------------------------------
// K1: compact mask rows -> index lists. Grid (NC, CSPLIT) = 300 blocks.
// Selection predicate "32-bit word != 0" is correct under both float32
// (1.0f = 0x3F800000) and int32 encodings of a 0/1 bool mask (established R5).
// List order is arbitrary; downstream sums of 0/1 spike values are exact in
// fp32 so order cannot change the result.
// ---------------------------------------------------------------------------
__global__ void __launch_bounds__(256)
k_compact(const int* __restrict__ mask)
{
    const int c   = blockIdx.x;
    const int y   = blockIdx.y;
    const int tid = threadIdx.x;

    const int4* m4 = (const int4*)(mask + (size_t)c * NNEUR);   // row base 16B-aligned
    int* out  = g_idx + c * MAXSEL;
    int* pcnt = g_nsel_pad + c * CPAD;

    const int i0 = y * (NNEUR / 4 / CSPLIT);          // 1250 int4 per y-slice
    const int i1 = i0 + (NNEUR / 4 / CSPLIT);
    for (int i = i0 + tid; i < i1; i += 256) {
        int4 v = m4[i];
        int n = 4 * i;
        if (v.x) { int p = atomicAdd(pcnt, 1); if (p < MAXSEL) out[p] = n;     }
        if (v.y) { int p = atomicAdd(pcnt, 1); if (p < MAXSEL) out[p] = n + 1; }
        if (v.z) { int p = atomicAdd(pcnt, 1); if (p < MAXSEL) out[p] = n + 2; }
        if (v.w) { int p = atomicAdd(pcnt, 1); if (p < MAXSEL) out[p] = n + 3; }
    }
}

// ---------------------------------------------------------------------------
// K2: gather — EXACT R5 body (measured 34.75us @ 5.3TB/s). Grid (NC, TSPLIT),
// 16 warps/block; each warp computes one timestep:
//   selected[c,t] = sum_{n in S_c} spikes[trial_c, t, n]
// No completion protocol here — that was the R6/R8 regression suspect.
// ---------------------------------------------------------------------------
__global__ void __launch_bounds__(WARPS_PER_BLK * 32)
k_gather(const float* __restrict__ spikes)
{
    __shared__ int s_idx[512];     // covers typical nsel (~15..250); spill path below
    const int c    = blockIdx.x;
    const int tid  = threadIdx.x;
    const int wid  = tid >> 5;
    const int lane = tid & 31;

    const int nsel = min(g_nsel_pad[c * CPAD], MAXSEL);
    const int* idx_g = g_idx + c * MAXSEL;
    const int ncache = nsel < 512 ? nsel : 512;
    for (int j = tid; j < ncache; j += blockDim.x) s_idx[j] = idx_g[j];
    __syncthreads();

    const int t = blockIdx.y * WARPS_PER_BLK + wid;
    if (t >= TUSE) return;

    const float* row = spikes + ((size_t)g_trials[c] * TFULL + t) * NNEUR;

    float s = 0.f;
    int j = lane;
    for (; j < ncache; j += 32) s += __ldg(row + s_idx[j]);
    for (; j < nsel;   j += 32) s += __ldg(row + __ldg(idx_g + j));

    #pragma unroll
    for (int o = 16; o > 0; o >>= 1)
        s += __shfl_down_sync(0xffffffffu, s, o);
    if (lane == 0) g_selected[c * TUSE + t] = s;
}

// ---------------------------------------------------------------------------
// K3: fano (warp-per-bin, shuffle-only, two-pass variance matching jnp.var
// ddof=0) + fused loss in the last-finishing block. Grid NC, 512 threads.
// ---------------------------------------------------------------------------
__global__ void __launch_bounds__(WARPS_PER_BLK * 32)
k_fano(const float* __restrict__ exp_fanos, float* __restrict__ out)
{
    __shared__ float sel[TUSE];
    __shared__ int   s_last;
    const int c    = blockIdx.x;
    const int tid  = threadIdx.x;
    const int wid  = tid >> 5;
    const int lane = tid & 31;

    for (int i = tid; i < TUSE; i += blockDim.x) sel[i] = g_selected[c * TUSE + i];
    __syncthreads();

    {   // warp 'wid' owns bin 'wid'
        const int b  = c_bins[wid];
        const int nb = TUSE / b;

        float sum = 0.f;
        for (int k = lane; k < nb; k += 32) {
            float cv = 0.f;
            const int base = k * b;
            for (int i = 0; i < b; i++) cv += sel[base + i];
            sum += cv;
        }
        #pragma unroll
        for (int o = 16; o > 0; o >>= 1)
            sum += __shfl_down_sync(0xffffffffu, sum, o);
        const float mean = __shfl_sync(0xffffffffu, sum, 0) / (float)nb;

        float vs = 0.f;
        for (int k = lane; k < nb; k += 32) {
            float cv = 0.f;
            const int base = k * b;
            for (int i = 0; i < b; i++) cv += sel[base + i];
            const float d = cv - mean;
            vs += d * d;
        }
        #pragma unroll
        for (int o = 16; o > 0; o >>= 1)
            vs += __shfl_down_sync(0xffffffffu, vs, o);
        if (lane == 0)
            g_fanos_c[c * NBINS + wid] = (vs / (float)nb) / fmaxf(mean, EPS_F);
    }

    // Last block computes the loss (release-RMW publish, acquire on consumer).
    __syncthreads();
    if (tid == 0) s_last = (atomic_add_release_gpu(&g_done2, 1) == NC - 1);
    __syncthreads();
    if (!s_last) return;
    if (tid == 0) fence_acq_rel_gpu();
    __syncthreads();

    if (wid == 0) {
        float sq = 0.f;
        if (lane < NBINS) {
            float ssum = 0.f;
            for (int cc = 0; cc < NC; cc++) ssum += g_fanos_c[cc * NBINS + lane];
            const float fano = ssum / (float)NC;
            const float d = exp_fanos[lane] - fano;
            sq = d * d;
        }
        #pragma unroll
        for (int o = 16; o > 0; o >>= 1)
            sq += __shfl_down_sync(0xffffffffu, sq, o);
        if (lane == 0) out[0] = 10.0f * (sq / (float)NBINS);
    }
}

// ---------------------------------------------------------------------------
extern "C" void kernel_launch(void* const* d_in, const int* in_sizes, int n_in,
                              void* d_out, int out_size)
{
    // Identify inputs by element count (robust to metadata ordering):
    //   spikes: 8*600*30000 = 144,000,000
    //   exp_fanos: 16
    //   sample_trials: 50
    //   sel_mask: 50*30000 = 1,500,000
    const float* spikes    = nullptr;
    const float* exp_fanos = nullptr;
    const void*  trials    = nullptr;
    const int*   mask      = nullptr;
    for (int i = 0; i < n_in; i++) {
        switch (in_sizes[i]) {
            case 144000000: spikes    = (const float*)d_in[i]; break;
            case 16:        exp_fanos = (const float*)d_in[i]; break;
            case 50:        trials    = d_in[i];               break;
            case 1500000:   mask      = (const int*)d_in[i];   break;
            default: break;
        }
    }
    float* out = (float*)d_out;

    k_init<<<1, 512>>>(trials);
    dim3 cgrid(NC, CSPLIT);
    k_compact<<<cgrid, 256>>>(mask);
    dim3 ggrid(NC, TSPLIT);
    k_gather<<<ggrid, WARPS_PER_BLK * 32>>>(spikes);
    k_fano<<<NC, WARPS_PER_BLK * 32>>>(exp_fanos, out);
}

// round 11
// speedup vs baseline: 1.7493x; 1.0833x over previous
#include <cuda_runtime.h>
#include <stdint.h>

// Problem constants (fixed by the reference's setup_inputs)
#define NC     50      // conditions
#define NNEUR  30000   // neurons (4-byte 0/1 elements; established R5)
#define TFULL  600     // full time length of spikes
#define TUSE   500     // T_END_MS - T_START_MS
#define NBINS  16      // len(BIN_MS)
#define MAXSEL 4096
#define EPS_F  1e-7f

#define WARPS_PER_BLK 16                                      // == NBINS
#define TSPLIT ((TUSE + WARPS_PER_BLK - 1) / WARPS_PER_BLK)   // 32 y-blocks per condition
#define CSPLIT 6                                              // compact y-split
#define CPAD   32                                             // counter padding (128 B)

__device__ __constant__ int c_bins[NBINS] = {1,1,2,3,4,6,9,13,18,26,38,55,78,113,162,234};

// Scratch (static device arrays — no allocation allowed)
__device__ float g_selected[NC * TUSE];
__device__ float g_fanos_c[NC * NBINS];
__device__ int   g_idx[NC * MAXSEL];     // compacted selected-neuron indices per condition
__device__ int   g_nsel_pad[NC * CPAD];  // padded per-condition counters
__device__ int   g_trials[NC];           // sanitized trial indices
__device__ int   g_done2;                // fano completion counter (for fused loss)

// Release-scoped atomic + acquire fence: last-block pattern without the
// CCTL.IVALL L1-flush of __threadfence().
__device__ __forceinline__ int atomic_add_release_gpu(int* p, int v)
{
    int old;
    asm volatile("atom.release.gpu.add.s32 %0, [%1], %2;"
                 : "=r"(old) : "l"(p), "r"(v) : "memory");
    return old;
}
__device__ __forceinline__ void fence_acq_rel_gpu()
{
    asm volatile("fence.acq_rel.gpu;" ::: "memory");
}

// ---------------------------------------------------------------------------
// K0: reset counters + sanitize trial indices. One block.
// ---------------------------------------------------------------------------
__global__ void __launch_bounds__(512)
k_init(const void* __restrict__ trials)
{
    const int tid = threadIdx.x;
    for (int i = tid; i < NC * CPAD; i += 512) g_nsel_pad[i] = 0;
    if (tid == 0) g_done2 = 0;
    if (tid < NC) {
        // Valid trial index in [0,8). If float-encoded, nonzero values
        // reinterpret as ints >= 0x3F800000 -> out of range -> convert.
        int iv = ((const int*)trials)[tid];
        if (iv < 0 || iv >= 8) iv = (int)(((const float*)trials)[tid]);
        g_trials[tid] = iv;
    }
}

// ---------------------------------------------------------------------------
// K1: compact mask rows -> index lists. Grid (NC, CSPLIT) = 300 blocks.
// Selection predicate "32-bit word != 0" is correct under both float32
// (1.0f = 0x3F800000) and int32 encodings of a 0/1 bool mask (established R5).
// List order is arbitrary; downstream sums of 0/1 spike values are exact in
// fp32 so order cannot change the result.
// ---------------------------------------------------------------------------
__global__ void __launch_bounds__(256)
k_compact(const int* __restrict__ mask)
{
    const int c   = blockIdx.x;
    const int y   = blockIdx.y;
    const int tid = threadIdx.x;

    const int4* m4 = (const int4*)(mask + (size_t)c * NNEUR);   // row base 16B-aligned
    int* out  = g_idx + c * MAXSEL;
    int* pcnt = g_nsel_pad + c * CPAD;

    const int i0 = y * (NNEUR / 4 / CSPLIT);          // 1250 int4 per y-slice
    const int i1 = i0 + (NNEUR / 4 / CSPLIT);
    for (int i = i0 + tid; i < i1; i += 256) {
        int4 v = m4[i];
        int n = 4 * i;
        if (v.x) { int p = atomicAdd(pcnt, 1); if (p < MAXSEL) out[p] = n;     }
        if (v.y) { int p = atomicAdd(pcnt, 1); if (p < MAXSEL) out[p] = n + 1; }
        if (v.z) { int p = atomicAdd(pcnt, 1); if (p < MAXSEL) out[p] = n + 2; }
        if (v.w) { int p = atomicAdd(pcnt, 1); if (p < MAXSEL) out[p] = n + 3; }
    }
}

// ---------------------------------------------------------------------------
// K2: gather — measured-good R5 body (~5.3 TB/s, near the 128B-line traffic
// floor). Grid (NC, TSPLIT), 16 warps/block; each warp computes one timestep:
//   selected[c,t] = sum_{n in S_c} spikes[trial_c, t, n]
// ---------------------------------------------------------------------------
__global__ void __launch_bounds__(WARPS_PER_BLK * 32)
k_gather(const float* __restrict__ spikes)
{
    __shared__ int s_idx[512];     // covers typical nsel (~15..250); spill path below
    const int c    = blockIdx.x;
    const int tid  = threadIdx.x;
    const int wid  = tid >> 5;
    const int lane = tid & 31;

    const int nsel = min(g_nsel_pad[c * CPAD], MAXSEL);
    const int* idx_g = g_idx + c * MAXSEL;
    const int ncache = nsel < 512 ? nsel : 512;
    for (int j = tid; j < ncache; j += blockDim.x) s_idx[j] = idx_g[j];
    __syncthreads();

    const int t = blockIdx.y * WARPS_PER_BLK + wid;
    if (t >= TUSE) return;

    const float* row = spikes + ((size_t)g_trials[c] * TFULL + t) * NNEUR;

    float s = 0.f;
    int j = lane;
    for (; j < ncache; j += 32) s += __ldg(row + s_idx[j]);
    for (; j < nsel;   j += 32) s += __ldg(row + __ldg(idx_g + j));

    #pragma unroll
    for (int o = 16; o > 0; o >>= 1)
        s += __shfl_down_sync(0xffffffffu, s, o);
    if (lane == 0) g_selected[c * TUSE + t] = s;
}

// ---------------------------------------------------------------------------
// K3: fano via PREFIX SUM + fused loss. Grid NC, 512 threads.
// sel[t] are small integers (spike counts), so the inclusive scan is EXACT in
// fp32; every bin count is then cnt_k = P[(k+1)b]-P[kb] — bit-identical to
// the reference's bin sums (2 LDS + 1 FSUB, no serial chains). Two-pass
// variance matches jnp.var (ddof=0).
// ---------------------------------------------------------------------------
__global__ void __launch_bounds__(512)
k_fano(const float* __restrict__ exp_fanos, float* __restrict__ out)
{
    __shared__ float S[512];       // S[i] = inclusive prefix: sel[0]+...+sel[i]
    __shared__ int   s_last;
    const int c    = blockIdx.x;
    const int tid  = threadIdx.x;
    const int wid  = tid >> 5;
    const int lane = tid & 31;

    S[tid] = (tid < TUSE) ? g_selected[c * TUSE + tid] : 0.f;
    __syncthreads();

    // Hillis-Steele inclusive scan (9 steps; exact: all values are integers)
    #pragma unroll
    for (int off = 1; off < 512; off <<= 1) {
        float v = (tid >= off) ? S[tid - off] : 0.f;
        __syncthreads();
        S[tid] += v;
        __syncthreads();
    }
    // P(i) := (i==0) ? 0 : S[i-1]

    {   // warp 'wid' owns bin size c_bins[wid]
        const int b  = c_bins[wid];
        const int nb = TUSE / b;

        const float total = S[nb * b - 1];            // exact integer
        const float mean  = total / (float)nb;

        float vs = 0.f;
        for (int k = lane; k < nb; k += 32) {
            const float lo  = k ? S[k * b - 1] : 0.f;
            const float cnt = S[k * b + b - 1] - lo;  // exact integer bin count
            const float d   = cnt - mean;
            vs += d * d;
        }
        #pragma unroll
        for (int o = 16; o > 0; o >>= 1)
            vs += __shfl_down_sync(0xffffffffu, vs, o);
        if (lane == 0)
            g_fanos_c[c * NBINS + wid] = (vs / (float)nb) / fmaxf(mean, EPS_F);
    }

    // Last block computes the loss (release-RMW publish, acquire on consumer).
    __syncthreads();
    if (tid == 0) s_last = (atomic_add_release_gpu(&g_done2, 1) == NC - 1);
    __syncthreads();
    if (!s_last) return;
    if (tid == 0) fence_acq_rel_gpu();
    __syncthreads();

    if (wid == 0) {
        float sq = 0.f;
        if (lane < NBINS) {
            float ssum = 0.f;
            for (int cc = 0; cc < NC; cc++) ssum += g_fanos_c[cc * NBINS + lane];
            const float fano = ssum / (float)NC;
            const float d = exp_fanos[lane] - fano;
            sq = d * d;
        }
        #pragma unroll
        for (int o = 16; o > 0; o >>= 1)
            sq += __shfl_down_sync(0xffffffffu, sq, o);
        if (lane == 0) out[0] = 10.0f * (sq / (float)NBINS);
    }
}

// ---------------------------------------------------------------------------
extern "C" void kernel_launch(void* const* d_in, const int* in_sizes, int n_in,
                              void* d_out, int out_size)
{
    // Identify inputs by element count (robust to metadata ordering):
    //   spikes: 8*600*30000 = 144,000,000
    //   exp_fanos: 16
    //   sample_trials: 50
    //   sel_mask: 50*30000 = 1,500,000
    const float* spikes    = nullptr;
    const float* exp_fanos = nullptr;
    const void*  trials    = nullptr;
    const int*   mask      = nullptr;
    for (int i = 0; i < n_in; i++) {
        switch (in_sizes[i]) {
            case 144000000: spikes    = (const float*)d_in[i]; break;
            case 16:        exp_fanos = (const float*)d_in[i]; break;
            case 50:        trials    = d_in[i];               break;
            case 1500000:   mask      = (const int*)d_in[i];   break;
            default: break;
        }
    }
    float* out = (float*)d_out;

    k_init<<<1, 512>>>(trials);
    dim3 cgrid(NC, CSPLIT);
    k_compact<<<cgrid, 256>>>(mask);
    dim3 ggrid(NC, TSPLIT);
    k_gather<<<ggrid, WARPS_PER_BLK * 32>>>(spikes);
    k_fano<<<NC, 512>>>(exp_fanos, out);
}

// round 14
// speedup vs baseline: 1.7562x; 1.0039x over previous
#include <cuda_runtime.h>
#include <stdint.h>

// Problem constants (fixed by the reference's setup_inputs)
#define NC     50      // conditions
#define NNEUR  30000   // neurons (4-byte 0/1 elements; established R5)
#define TFULL  600     // full time length of spikes
#define TUSE   500     // T_END_MS - T_START_MS
#define NBINS  16      // len(BIN_MS)
#define MAXSEL 4096
#define EPS_F  1e-7f

#define WARPS_PER_BLK 16                                      // == NBINS
#define TSPLIT ((TUSE + WARPS_PER_BLK - 1) / WARPS_PER_BLK)   // 32 y-blocks per condition
#define CSPLIT    6                                           // compact y-split
#define SLICE_I4  (NNEUR / 4 / CSPLIT)                        // 1250 int4 per slice
#define CHUNK_I4  5                                           // int4 per thread (5*256 >= 1250)
#define SLICE_CAP 640                                         // 6*640 = 3840 <= MAXSEL

__device__ __constant__ int c_bins[NBINS] = {1,1,2,3,4,6,9,13,18,26,38,55,78,113,162,234};

// Scratch (static device arrays — no allocation allowed)
__device__ float g_selected[NC * TUSE];
__device__ float g_fanos_c[NC * NBINS];
__device__ int   g_idx[NC * MAXSEL];     // per-condition, per-slice ordered index lists
__device__ int   g_scnt[NC * 8];         // per-slice selected counts
__device__ int   g_trials[NC];           // sanitized trial indices
__device__ int   g_done2;                // fano completion counter (reset in k_compact)

// Release-scoped atomic + acquire fence: last-block pattern without the
// CCTL.IVALL L1-flush of __threadfence().
__device__ __forceinline__ int atomic_add_release_gpu(int* p, int v)
{
    int old;
    asm volatile("atom.release.gpu.add.s32 %0, [%1], %2;"
                 : "=r"(old) : "l"(p), "r"(v) : "memory");
    return old;
}
__device__ __forceinline__ void fence_acq_rel_gpu()
{
    asm volatile("fence.acq_rel.gpu;" ::: "memory");
}

// ---------------------------------------------------------------------------
// K1: ordered atomic-free compact. Grid (NC, CSPLIT) = 300 blocks, 256 thr.
// Each thread owns a contiguous 5-int4 chunk: count -> block shuffle-scan ->
// ordered write. Output per (c,y) slice region is SORTED ascending; counts in
// g_scnt. No global counters -> nothing to reset -> k_init deleted.
// Selection predicate "32-bit word != 0" is correct under both float32
// (1.0f = 0x3F800000) and int32 encodings of a 0/1 bool mask (established R5).
// Block (0,0) also sanitizes trial indices and resets g_done2 (kernel
// ordering = happens-before all consumers).
// ---------------------------------------------------------------------------
__global__ void __launch_bounds__(256)
k_compact(const int* __restrict__ mask, const void* __restrict__ trials)
{
    __shared__ int wtot[8];
    const int c    = blockIdx.x;
    const int y    = blockIdx.y;
    const int tid  = threadIdx.x;
    const int lane = tid & 31;
    const int wid  = tid >> 5;

    if (c == 0 && y == 0) {
        if (tid == 0) g_done2 = 0;
        if (tid < NC) {
            // Valid trial index in [0,8). If float-encoded, nonzero values
            // reinterpret as ints >= 0x3F800000 -> out of range -> convert.
            int iv = ((const int*)trials)[tid];
            if (iv < 0 || iv >= 8) iv = (int)(((const float*)trials)[tid]);
            g_trials[tid] = iv;
        }
    }

    const int4* m4 = (const int4*)(mask + (size_t)c * NNEUR) + y * SLICE_I4;
    const int i0 = tid * CHUNK_I4;
    const int i1 = (i0 + CHUNK_I4 < SLICE_I4) ? i0 + CHUNK_I4 : SLICE_I4;

    // Pass 1: load chunk into registers, count selected.
    int4 v[CHUNK_I4];
    int cnt = 0;
    #pragma unroll
    for (int k = 0; k < CHUNK_I4; k++) {
        if (i0 + k < i1) {
            v[k] = m4[i0 + k];
            cnt += (v[k].x != 0) + (v[k].y != 0) + (v[k].z != 0) + (v[k].w != 0);
        }
    }

    // Block exclusive scan of cnt (warp shuffle scan + warp totals).
    int inc = cnt;
    #pragma unroll
    for (int o = 1; o < 32; o <<= 1) {
        int n = __shfl_up_sync(0xffffffffu, inc, o);
        if (lane >= o) inc += n;
    }
    if (lane == 31) wtot[wid] = inc;
    __syncthreads();
    int woff = 0;
    #pragma unroll
    for (int w = 0; w < 8; w++) woff += (w < wid) ? wtot[w] : 0;
    int p = woff + inc - cnt;            // exclusive offset for this thread

    // Pass 2: ordered write (ascending neuron indices).
    int* out = g_idx + c * MAXSEL + y * SLICE_CAP;
    #pragma unroll
    for (int k = 0; k < CHUNK_I4; k++) {
        if (i0 + k < i1) {
            const int n = (y * SLICE_I4 + i0 + k) * 4;
            if (v[k].x && p < SLICE_CAP) out[p++] = n;
            if (v[k].y && p < SLICE_CAP) out[p++] = n + 1;
            if (v[k].z && p < SLICE_CAP) out[p++] = n + 2;
            if (v[k].w && p < SLICE_CAP) out[p++] = n + 3;
        }
    }
    if (tid == 0) {
        int tot = 0;
        #pragma unroll
        for (int w = 0; w < 8; w++) tot += wtot[w];
        g_scnt[c * 8 + y] = (tot < SLICE_CAP) ? tot : SLICE_CAP;
    }
}

// ---------------------------------------------------------------------------
// K2: gather. Grid (NC, TSPLIT), 16 warps/block; each warp computes one
// timestep: selected[c,t] = sum_{n in S_c} spikes[trial_c, t, n].
// Indices staged to shared from the per-slice regions (sorted ascending ->
// better DRAM locality); hot loop is flat, all indices always in shared.
// ---------------------------------------------------------------------------
__global__ void __launch_bounds__(WARPS_PER_BLK * 32)
k_gather(const float* __restrict__ spikes)
{
    __shared__ int s_idx[CSPLIT * SLICE_CAP];   // 3840 ints = 15 KB
    __shared__ int s_off[CSPLIT + 1];
    const int c    = blockIdx.x;
    const int tid  = threadIdx.x;
    const int wid  = tid >> 5;
    const int lane = tid & 31;

    if (tid == 0) {
        int acc = 0;
        #pragma unroll
        for (int y = 0; y < CSPLIT; y++) { s_off[y] = acc; acc += g_scnt[c * 8 + y]; }
        s_off[CSPLIT] = acc;
    }
    __syncthreads();
    #pragma unroll
    for (int y = 0; y < CSPLIT; y++) {
        const int base = s_off[y];
        const int cnt  = s_off[y + 1] - base;
        for (int j = tid; j < cnt; j += WARPS_PER_BLK * 32)
            s_idx[base + j] = g_idx[c * MAXSEL + y * SLICE_CAP + j];
    }
    __syncthreads();

    const int nsel = s_off[CSPLIT];
    const int t = blockIdx.y * WARPS_PER_BLK + wid;
    if (t >= TUSE) return;

    const float* row = spikes + ((size_t)g_trials[c] * TFULL + t) * NNEUR;

    float s = 0.f;
    for (int j = lane; j < nsel; j += 32) s += __ldg(row + s_idx[j]);

    #pragma unroll
    for (int o = 16; o > 0; o >>= 1)
        s += __shfl_down_sync(0xffffffffu, s, o);
    if (lane == 0) g_selected[c * TUSE + t] = s;
}

// ---------------------------------------------------------------------------
// K3: fano via warp-shuffle prefix sum + fused loss. Grid NC, 512 threads.
// sel[t] are small integers, so the scan is EXACT in fp32; every bin count is
// cnt_k = P[(k+1)b]-P[kb] — bit-identical to the reference's bin sums.
// Only 3 block barriers (vs 18 in the Hillis-Steele version).
// Two-pass variance matches jnp.var (ddof=0).
// ---------------------------------------------------------------------------
__global__ void __launch_bounds__(512)
k_fano(const float* __restrict__ exp_fanos, float* __restrict__ out)
{
    __shared__ float S[512];       // inclusive prefix sums
    __shared__ float winc[16];     // per-warp inclusive totals
    __shared__ int   s_last;
    const int c    = blockIdx.x;
    const int tid  = threadIdx.x;
    const int wid  = tid >> 5;
    const int lane = tid & 31;

    float v = (tid < TUSE) ? g_selected[c * TUSE + tid] : 0.f;

    // Warp inclusive scan (5 shuffle steps; exact: integer values).
    #pragma unroll
    for (int o = 1; o < 32; o <<= 1) {
        float n = __shfl_up_sync(0xffffffffu, v, o);
        if (lane >= o) v += n;
    }
    if (lane == 31) winc[wid] = v;
    __syncthreads();
    if (wid == 0) {
        float w = winc[lane & 15];
        #pragma unroll
        for (int o = 1; o < 16; o <<= 1) {
            float n = __shfl_up_sync(0xffffffffu, w, o);
            if ((lane & 15) >= o) w += n;
        }
        if (lane < 16) winc[lane] = w;    // inclusive warp-total prefix
    }
    __syncthreads();
    S[tid] = v + (wid ? winc[wid - 1] : 0.f);
    __syncthreads();
    // P(i) := (i==0) ? 0 : S[i-1]

    {   // warp 'wid' owns bin size c_bins[wid]
        const int b  = c_bins[wid];
        const int nb = TUSE / b;

        const float total = S[nb * b - 1];            // exact integer
        const float mean  = total / (float)nb;

        float vs = 0.f;
        for (int k = lane; k < nb; k += 32) {
            const float lo  = k ? S[k * b - 1] : 0.f;
            const float cnt = S[k * b + b - 1] - lo;  // exact integer bin count
            const float d   = cnt - mean;
            vs += d * d;
        }
        #pragma unroll
        for (int o = 16; o > 0; o >>= 1)
            vs += __shfl_down_sync(0xffffffffu, vs, o);
        if (lane == 0)
            g_fanos_c[c * NBINS + wid] = (vs / (float)nb) / fmaxf(mean, EPS_F);
    }

    // Last block computes the loss (release-RMW publish, acquire on consumer).
    __syncthreads();
    if (tid == 0) s_last = (atomic_add_release_gpu(&g_done2, 1) == NC - 1);
    __syncthreads();
    if (!s_last) return;
    if (tid == 0) fence_acq_rel_gpu();
    __syncthreads();

    if (wid == 0) {
        float sq = 0.f;
        if (lane < NBINS) {
            float ssum = 0.f;
            #pragma unroll
            for (int cc = 0; cc < NC; cc++) ssum += g_fanos_c[cc * NBINS + lane];
            const float fano = ssum / (float)NC;
            const float d = exp_fanos[lane] - fano;
            sq = d * d;
        }
        #pragma unroll
        for (int o = 16; o > 0; o >>= 1)
            sq += __shfl_down_sync(0xffffffffu, sq, o);
        if (lane == 0) out[0] = 10.0f * (sq / (float)NBINS);
    }
}

// ---------------------------------------------------------------------------
extern "C" void kernel_launch(void* const* d_in, const int* in_sizes, int n_in,
                              void* d_out, int out_size)
{
    // Identify inputs by element count (robust to metadata ordering):
    //   spikes: 8*600*30000 = 144,000,000
    //   exp_fanos: 16
    //   sample_trials: 50
    //   sel_mask: 50*30000 = 1,500,000
    const float* spikes    = nullptr;
    const float* exp_fanos = nullptr;
    const void*  trials    = nullptr;
    const int*   mask      = nullptr;
    for (int i = 0; i < n_in; i++) {
        switch (in_sizes[i]) {
            case 144000000: spikes    = (const float*)d_in[i]; break;
            case 16:        exp_fanos = (const float*)d_in[i]; break;
            case 50:        trials    = d_in[i];               break;
            case 1500000:   mask      = (const int*)d_in[i];   break;
            default: break;
        }
    }
    float* out = (float*)d_out;

    dim3 cgrid(NC, CSPLIT);
    k_compact<<<cgrid, 256>>>(mask, trials);
    dim3 ggrid(NC, TSPLIT);
    k_gather<<<ggrid, WARPS_PER_BLK * 32>>>(spikes);
    k_fano<<<NC, 512>>>(exp_fanos, out);
}